// round 8
// baseline (speedup 1.0000x reference)
#include <cuda_runtime.h>

// AtomicNeuralNetwork: species-routed per-atom MLP [39 -> 50 silu -> 50 silu -> 1]
// N=4096 samples, A=256 atoms, S=8 species. Output [N, A] fp32.
//
// One block = (1 atom, 256-sample tile). The block's desc tile (256 x 39) is
// cooperatively staged into smem with coalesced LDGs (per-thread direct loads
// would be stride-39936B across lanes -> 32 L1tex wavefronts per LDG). Species
// weights live in smem, padded H 50->52; all MACs use packed fma.rn.f32x2
// (2x the rate of 3-reg FFMA on sm_103a). Weight LDS are warp-uniform ->
// broadcast. Occupancy 2 overlaps one CTA's staging with the other's compute
// (regs: peak live ~115 < 128-reg cap; smem 2x59.1KB < 227KB).

#define NN   4096
#define AA   256
#define DIN  39
#define HH   50
#define HP   52      // padded hidden dim
#define TPB  256

// dynamic smem layout (float offsets); all 16B-aligned for LDS.128
#define OFF_X   0                      // 256*39  = 9984
#define OFF_W1  (OFF_X  + TPB * DIN)   // 39*52   = 2028
#define OFF_W2  (OFF_W1 + DIN * HP)    // 50*52   = 2600
#define OFF_B1  (OFF_W2 + HH * HP)     // 52
#define OFF_B2  (OFF_B1 + HP)          // 52
#define OFF_W3  (OFF_B2 + HP)          // 52
#define OFF_B3  (OFF_W3 + HP)          // 1
#define SMEM_FLOATS (OFF_B3 + 4)       // pad
#define SMEM_BYTES  (SMEM_FLOATS * 4)  // ~59.1 KB

typedef unsigned long long u64;

__device__ __forceinline__ u64 pack2_dup(float v) {
    u64 r; asm("mov.b64 %0, {%1, %1};" : "=l"(r) : "f"(v)); return r;
}
__device__ __forceinline__ void unpack2(u64 v, float& lo, float& hi) {
    asm("mov.b64 {%0, %1}, %2;" : "=f"(lo), "=f"(hi) : "l"(v));
}
__device__ __forceinline__ u64 pack2(float lo, float hi) {
    u64 r; asm("mov.b64 %0, {%1, %2};" : "=l"(r) : "f"(lo), "f"(hi)); return r;
}
// packed dual-FMA: d = a*b + c on both f32 lanes
__device__ __forceinline__ u64 fma2(u64 a, u64 b, u64 c) {
    u64 d; asm("fma.rn.f32x2 %0, %1, %2, %3;" : "=l"(d) : "l"(a), "l"(b), "l"(c));
    return d;
}
__device__ __forceinline__ float silu_f(float v) {
    return __fdividef(v, 1.0f + __expf(-v));   // MUFU.EX2 + MUFU.RCP
}

extern __shared__ float smem[];

__global__ void __launch_bounds__(TPB, 2)
atomic_mlp_kernel(const float* __restrict__ desc,
                  const int*   __restrict__ numbers,
                  const float* __restrict__ W1, const float* __restrict__ B1,
                  const float* __restrict__ W2, const float* __restrict__ B2,
                  const float* __restrict__ W3, const float* __restrict__ B3,
                  float* __restrict__ out)
{
    float* sX  = smem + OFF_X;    // [256][39]
    float* sW1 = smem + OFF_W1;   // [39][52], padded cols zero
    float* sW2 = smem + OFF_W2;   // [50][52], padded cols zero
    float* sB1 = smem + OFF_B1;
    float* sB2 = smem + OFF_B2;
    float* sW3 = smem + OFF_W3;
    float* sB3 = smem + OFF_B3;

    const int a    = blockIdx.x;   // atom
    const int tile = blockIdx.y;   // sample tile
    const int tid  = threadIdx.x;
    const int s    = numbers[a];   // species

    // ---- coalesced staging of the desc tile: rows n = tile*256 .. +255 ----
    // i = r*DIN + c walked incrementally (no integer divide per iteration).
    {
        const float* base = desc + ((long)tile * TPB * AA + a) * DIN;
        int r = tid / DIN, c = tid - r * DIN;          // once
        for (int i = tid; i < TPB * DIN; i += TPB) {
            sX[i] = base[(long)r * AA * DIN + c];
            c += TPB - ((TPB / DIN) + 1) * DIN;        // c += 256 - 7*39 = -17
            r += (TPB / DIN) + 1;                      // r += 7
            if (c < 0) { c += DIN; r -= 1; }           // renormalize
        }
    }

    // ---- stage padded weights ----
    for (int i = tid; i < DIN * HP; i += TPB) {
        int d = i / HP, h = i - d * HP;
        sW1[i] = (h < HH) ? W1[(s * DIN + d) * HH + h] : 0.0f;
    }
    for (int i = tid; i < HH * HP; i += TPB) {
        int hi_ = i / HP, ho = i - hi_ * HP;
        sW2[i] = (ho < HH) ? W2[(s * HH + hi_) * HH + ho] : 0.0f;
    }
    if (tid < HP) {
        sB1[tid] = (tid < HH) ? B1[s * HH + tid] : 0.0f;
        sB2[tid] = (tid < HH) ? B2[s * HH + tid] : 0.0f;
        sW3[tid] = (tid < HH) ? W3[s * HH + tid] : 0.0f;
    }
    if (tid == 0) sB3[0] = B3[s];
    __syncthreads();

    const float* xrow = sX + tid * DIN;   // bank-stride 7 across lanes: conflict-free

    // ---- layer 1: [39] -> [52] ----
    u64 acc[HP / 2];
    {
        const u64* bp = (const u64*)sB1;
        #pragma unroll
        for (int j = 0; j < HP / 2; j++) acc[j] = bp[j];
    }
    #pragma unroll
    for (int d = 0; d < DIN; d++) {
        const u64 xv = pack2_dup(xrow[d]);
        const ulonglong2* row = (const ulonglong2*)(sW1 + d * HP);  // uniform -> broadcast
        #pragma unroll
        for (int j = 0; j < HP / 4; j++) {
            ulonglong2 w = row[j];                     // LDS.128 = 4 weights
            acc[2 * j]     = fma2(xv, w.x, acc[2 * j]);
            acc[2 * j + 1] = fma2(xv, w.y, acc[2 * j + 1]);
        }
    }
    float h1[HH];
    #pragma unroll
    for (int j = 0; j < HH / 2; j++) {
        float lo, hi; unpack2(acc[j], lo, hi);
        h1[2 * j]     = silu_f(lo);
        h1[2 * j + 1] = silu_f(hi);
    }

    // ---- layer 2: [50] -> [52] ----
    u64 acc2[HP / 2];
    {
        const u64* bp = (const u64*)sB2;
        #pragma unroll
        for (int j = 0; j < HP / 2; j++) acc2[j] = bp[j];
    }
    #pragma unroll
    for (int k = 0; k < HH; k++) {
        const u64 xv = pack2_dup(h1[k]);
        const ulonglong2* row = (const ulonglong2*)(sW2 + k * HP);
        #pragma unroll
        for (int j = 0; j < HP / 4; j++) {
            ulonglong2 w = row[j];
            acc2[2 * j]     = fma2(xv, w.x, acc2[2 * j]);
            acc2[2 * j + 1] = fma2(xv, w.y, acc2[2 * j + 1]);
        }
    }

    // ---- layer 3: [52] -> 1 ----
    u64 a3 = 0ull;
    const u64* w3p = (const u64*)sW3;
    #pragma unroll
    for (int j = 0; j < HP / 2; j++) {
        float lo, hi; unpack2(acc2[j], lo, hi);
        u64 hv = pack2(silu_f(lo), silu_f(hi));       // padded lanes: w3 = 0
        a3 = fma2(hv, w3p[j], a3);
    }
    float lo, hi; unpack2(a3, lo, hi);
    const int n = tile * TPB + tid;
    out[(long)n * AA + a] = lo + hi + sB3[0];
}

extern "C" void kernel_launch(void* const* d_in, const int* in_sizes, int n_in,
                              void* d_out, int out_size)
{
    const float* desc    = (const float*)d_in[0];
    const int*   numbers = (const int*)  d_in[1];
    const float* W1      = (const float*)d_in[2];
    const float* B1      = (const float*)d_in[3];
    const float* W2      = (const float*)d_in[4];
    const float* B2      = (const float*)d_in[5];
    const float* W3      = (const float*)d_in[6];
    const float* B3      = (const float*)d_in[7];
    float* out = (float*)d_out;

    // Unconditional (no static guards per harness rules); non-stream API,
    // legal during graph capture.
    cudaFuncSetAttribute(atomic_mlp_kernel,
                         cudaFuncAttributeMaxDynamicSharedMemorySize,
                         SMEM_BYTES);

    dim3 grid(AA, NN / TPB);   // 256 atoms x 16 sample tiles
    atomic_mlp_kernel<<<grid, TPB, SMEM_BYTES>>>(desc, numbers,
                                                 W1, B1, W2, B2, W3, B3, out);
}